// round 1
// baseline (speedup 1.0000x reference)
#include <cuda_runtime.h>
#include <cstdint>

// Problem constants
#define BB   4
#define CCH  256
#define NPX  4096     // W*H = 64*64
#define CQ   64       // C/4

#define OUT_ELEMS  ((size_t)BB * CCH * NPX)          // 4,194,304
#define ATTN_ELEMS ((size_t)BB * NPX * NPX)          // 67,108,864

// Scratch: Q^T and K^T stored as [b][n][cq] (K-contiguous for NT GEMM)
__device__ float g_Qt[BB * NPX * CQ];
__device__ float g_Kt[BB * NPX * CQ];
// Fallback attention buffer in case d_out only holds `out`
__device__ float g_attn_fb[ATTN_ELEMS];

// ---------------------------------------------------------------------------
// Kernel 1: projection. outT[b][n][oc] = sum_c w[oc][c] * x[b][c][n] + bias[oc]
// Block: 64 tokens (n) x 64 out-channels. 256 threads, 4x4 microtile.
// ---------------------------------------------------------------------------
__global__ void proj_kernel(const float* __restrict__ x,
                            const float* __restrict__ w,
                            const float* __restrict__ bias,
                            float* __restrict__ outT)
{
    const int b  = blockIdx.y;
    const int n0 = blockIdx.x * 64;
    const int tid = threadIdx.x;
    const int tx = tid & 15;        // n dimension
    const int ty = tid >> 4;        // oc dimension

    __shared__ __align__(16) float Xs[32][64];   // [c][n]
    __shared__ __align__(16) float Wt[32][68];   // [c][oc], padded pitch (272B, 16B-mult)

    const float* xb = x + (size_t)b * CCH * NPX;

    float acc[4][4];
#pragma unroll
    for (int i = 0; i < 4; i++)
#pragma unroll
        for (int j = 0; j < 4; j++) acc[i][j] = 0.f;

    for (int c0 = 0; c0 < CCH; c0 += 32) {
        // X tile: 32c x 64n = 512 float4, 2 per thread (coalesced along n)
#pragma unroll
        for (int r = 0; r < 2; r++) {
            int idx = tid + r * 256;
            int cc  = idx >> 4;
            int nq  = (idx & 15) << 2;
            float4 v = *(const float4*)(xb + (size_t)(c0 + cc) * NPX + n0 + nq);
            *(float4*)(&Xs[cc][nq]) = v;
        }
        // W tile transposed: Wt[cc][oc], 64oc x 32c = 512 float4, 2 per thread
#pragma unroll
        for (int r = 0; r < 2; r++) {
            int idx = tid + r * 256;
            int oc  = idx >> 3;
            int cq  = (idx & 7) << 2;
            float4 v = *(const float4*)(w + oc * CCH + c0 + cq);
            Wt[cq + 0][oc] = v.x;
            Wt[cq + 1][oc] = v.y;
            Wt[cq + 2][oc] = v.z;
            Wt[cq + 3][oc] = v.w;
        }
        __syncthreads();
#pragma unroll
        for (int cc = 0; cc < 32; cc++) {
            float4 a  = *(const float4*)(&Wt[cc][ty * 4]);
            float4 bv = *(const float4*)(&Xs[cc][tx * 4]);
            float av[4] = {a.x, a.y, a.z, a.w};
            float bw[4] = {bv.x, bv.y, bv.z, bv.w};
#pragma unroll
            for (int i = 0; i < 4; i++)
#pragma unroll
                for (int j = 0; j < 4; j++)
                    acc[i][j] = fmaf(av[i], bw[j], acc[i][j]);
        }
        __syncthreads();
    }

    float4 bb = *(const float4*)(bias + ty * 4);
    float b4[4] = {bb.x, bb.y, bb.z, bb.w};
    float* ob = outT + (size_t)b * NPX * CQ;
#pragma unroll
    for (int j = 0; j < 4; j++) {
        int n = n0 + tx * 4 + j;
        float4 v = make_float4(acc[0][j] + b4[0], acc[1][j] + b4[1],
                               acc[2][j] + b4[2], acc[3][j] + b4[3]);
        *(float4*)(ob + (size_t)n * CQ + ty * 4) = v;
    }
}

// ---------------------------------------------------------------------------
// Kernel 2: energy[b][i][j] = sum_c Qt[b][i][c] * Kt[b][j][c]   (K = 64)
// Block: 64i x 64j, full K staged once. 256 threads, 4x4 microtile.
// ---------------------------------------------------------------------------
__global__ void energy_kernel(float* __restrict__ E)
{
    const int b  = blockIdx.z;
    const int i0 = blockIdx.y * 64;
    const int j0 = blockIdx.x * 64;
    const int tid = threadIdx.x;
    const int tx = tid & 15;        // j
    const int ty = tid >> 4;        // i

    __shared__ __align__(16) float Qs[64][68];   // [c][i]
    __shared__ __align__(16) float Ks[64][68];   // [c][j]

    const float* Qb = g_Qt + (size_t)b * NPX * CQ;
    const float* Kb = g_Kt + (size_t)b * NPX * CQ;

    // Load both 64x64 tiles (1024 float4 each -> 4 per thread), scatter transposed
#pragma unroll
    for (int r = 0; r < 4; r++) {
        int idx = tid + r * 256;          // f4 index 0..1023
        int row = idx >> 4;               // 0..63
        int cq  = (idx & 15) << 2;        // 0..60
        float4 q = *(const float4*)(Qb + (size_t)(i0 + row) * CQ + cq);
        Qs[cq + 0][row] = q.x; Qs[cq + 1][row] = q.y;
        Qs[cq + 2][row] = q.z; Qs[cq + 3][row] = q.w;
        float4 k = *(const float4*)(Kb + (size_t)(j0 + row) * CQ + cq);
        Ks[cq + 0][row] = k.x; Ks[cq + 1][row] = k.y;
        Ks[cq + 2][row] = k.z; Ks[cq + 3][row] = k.w;
    }
    __syncthreads();

    float acc[4][4];
#pragma unroll
    for (int i = 0; i < 4; i++)
#pragma unroll
        for (int j = 0; j < 4; j++) acc[i][j] = 0.f;

#pragma unroll 16
    for (int c = 0; c < 64; c++) {
        float4 a  = *(const float4*)(&Qs[c][ty * 4]);
        float4 bv = *(const float4*)(&Ks[c][tx * 4]);
        float av[4] = {a.x, a.y, a.z, a.w};
        float bw[4] = {bv.x, bv.y, bv.z, bv.w};
#pragma unroll
        for (int i = 0; i < 4; i++)
#pragma unroll
            for (int j = 0; j < 4; j++)
                acc[i][j] = fmaf(av[i], bw[j], acc[i][j]);
    }

    float* Eb = E + (size_t)b * NPX * NPX;
#pragma unroll
    for (int i = 0; i < 4; i++) {
        int ii = i0 + ty * 4 + i;
        *(float4*)(Eb + (size_t)ii * NPX + j0 + tx * 4) =
            make_float4(acc[i][0], acc[i][1], acc[i][2], acc[i][3]);
    }
}

// ---------------------------------------------------------------------------
// Kernel 3: row softmax in place. One block (256 thr) per row of 4096.
// ---------------------------------------------------------------------------
__global__ void softmax_kernel(float* __restrict__ attn)
{
    __shared__ float red[8];
    const size_t row = blockIdx.x;
    float* r = attn + row * NPX;
    const int t = threadIdx.x;
    const int lane = t & 31;
    const int warp = t >> 5;

    float4 v[4];
#pragma unroll
    for (int u = 0; u < 4; u++)
        v[u] = *(const float4*)(r + (size_t)(t + u * 256) * 4);

    float mx = -3.402823e38f;
#pragma unroll
    for (int u = 0; u < 4; u++) {
        mx = fmaxf(mx, fmaxf(fmaxf(v[u].x, v[u].y), fmaxf(v[u].z, v[u].w)));
    }
#pragma unroll
    for (int o = 16; o > 0; o >>= 1)
        mx = fmaxf(mx, __shfl_xor_sync(0xFFFFFFFFu, mx, o));
    if (lane == 0) red[warp] = mx;
    __syncthreads();
    float rowmax = red[0];
#pragma unroll
    for (int u = 1; u < 8; u++) rowmax = fmaxf(rowmax, red[u]);
    __syncthreads();

    float s = 0.f;
#pragma unroll
    for (int u = 0; u < 4; u++) {
        v[u].x = __expf(v[u].x - rowmax);
        v[u].y = __expf(v[u].y - rowmax);
        v[u].z = __expf(v[u].z - rowmax);
        v[u].w = __expf(v[u].w - rowmax);
        s += v[u].x + v[u].y + v[u].z + v[u].w;
    }
#pragma unroll
    for (int o = 16; o > 0; o >>= 1)
        s += __shfl_xor_sync(0xFFFFFFFFu, s, o);
    if (lane == 0) red[warp] = s;
    __syncthreads();
    float total = 0.f;
#pragma unroll
    for (int u = 0; u < 8; u++) total += red[u];
    float inv = 1.0f / total;

#pragma unroll
    for (int u = 0; u < 4; u++) {
        v[u].x *= inv; v[u].y *= inv; v[u].z *= inv; v[u].w *= inv;
        *(float4*)(r + (size_t)(t + u * 256) * 4) = v[u];
    }
}

// ---------------------------------------------------------------------------
// Kernel 4: out[b][c][m] = gamma * (sum_n x[b][c][n] * attn[b][m][n]) + x[b][c][m]
// NT GEMM: M=256 (c), N=4096 (m), K=4096 (n). 64x64 tile, BK=16, 256 threads.
// ---------------------------------------------------------------------------
__global__ void out_kernel(const float* __restrict__ x,
                           const float* __restrict__ attn,
                           const float* __restrict__ gamma,
                           float* __restrict__ outp)
{
    const int b  = blockIdx.z;
    const int c0 = blockIdx.y * 64;
    const int m0 = blockIdx.x * 64;
    const int tid = threadIdx.x;
    const int tx = tid & 15;        // m
    const int ty = tid >> 4;        // c

    __shared__ __align__(16) float As[16][68];   // [k][c]
    __shared__ __align__(16) float Bs[16][68];   // [k][m]

    const float* A  = x    + (size_t)b * CCH * NPX;   // [256][4096]
    const float* Bm = attn + (size_t)b * NPX * NPX;   // [4096][4096]

    const int lm = tid >> 2;          // 0..63 row within tile
    const int lk = (tid & 3) << 2;    // 0,4,8,12

    const float* Aptr = A  + (size_t)(c0 + lm) * NPX + lk;
    const float* Bptr = Bm + (size_t)(m0 + lm) * NPX + lk;

    float acc[4][4];
#pragma unroll
    for (int i = 0; i < 4; i++)
#pragma unroll
        for (int j = 0; j < 4; j++) acc[i][j] = 0.f;

    float4 av = *(const float4*)Aptr;
    float4 bv = *(const float4*)Bptr;

    for (int k0 = 0; k0 < NPX; k0 += 16) {
        As[lk + 0][lm] = av.x; As[lk + 1][lm] = av.y;
        As[lk + 2][lm] = av.z; As[lk + 3][lm] = av.w;
        Bs[lk + 0][lm] = bv.x; Bs[lk + 1][lm] = bv.y;
        Bs[lk + 2][lm] = bv.z; Bs[lk + 3][lm] = bv.w;
        __syncthreads();

        if (k0 + 16 < NPX) {
            av = *(const float4*)(Aptr + k0 + 16);
            bv = *(const float4*)(Bptr + k0 + 16);
        }

#pragma unroll
        for (int k = 0; k < 16; k++) {
            float4 a = *(const float4*)(&As[k][ty * 4]);
            float4 bq = *(const float4*)(&Bs[k][tx * 4]);
            float arr[4] = {a.x, a.y, a.z, a.w};
            float brr[4] = {bq.x, bq.y, bq.z, bq.w};
#pragma unroll
            for (int i = 0; i < 4; i++)
#pragma unroll
                for (int j = 0; j < 4; j++)
                    acc[i][j] = fmaf(arr[i], brr[j], acc[i][j]);
        }
        __syncthreads();
    }

    const float g = gamma[0];
    float* ob = outp + (size_t)b * CCH * NPX;
#pragma unroll
    for (int i = 0; i < 4; i++) {
        int c = c0 + ty * 4 + i;
        float4 xv = *(const float4*)(A + (size_t)c * NPX + m0 + tx * 4);
        float4 v = make_float4(fmaf(g, acc[i][0], xv.x),
                               fmaf(g, acc[i][1], xv.y),
                               fmaf(g, acc[i][2], xv.z),
                               fmaf(g, acc[i][3], xv.w));
        *(float4*)(ob + (size_t)c * NPX + m0 + tx * 4) = v;
    }
}

// ---------------------------------------------------------------------------
// Launch
// ---------------------------------------------------------------------------
extern "C" void kernel_launch(void* const* d_in, const int* in_sizes, int n_in,
                              void* d_out, int out_size)
{
    const float* x     = (const float*)d_in[0];
    const float* w_q   = (const float*)d_in[1];
    const float* b_q   = (const float*)d_in[2];
    const float* w_k   = (const float*)d_in[3];
    const float* b_k   = (const float*)d_in[4];
    const float* gamma = (const float*)d_in[5];

    float* outp = (float*)d_out;

    // Attention destination: tuple output (out, attention) flattened -> after out.
    float* attn;
    if ((size_t)out_size >= OUT_ELEMS + ATTN_ELEMS) {
        attn = outp + OUT_ELEMS;
    } else {
        void* p = nullptr;
        cudaGetSymbolAddress(&p, g_attn_fb);
        attn = (float*)p;
    }

    void* pq = nullptr; void* pk = nullptr;
    cudaGetSymbolAddress(&pq, g_Qt);
    cudaGetSymbolAddress(&pk, g_Kt);

    dim3 gp(NPX / 64, BB);
    proj_kernel<<<gp, 256>>>(x, w_q, b_q, (float*)pq);
    proj_kernel<<<gp, 256>>>(x, w_k, b_k, (float*)pk);

    dim3 ge(NPX / 64, NPX / 64, BB);
    energy_kernel<<<ge, 256>>>(attn);

    softmax_kernel<<<BB * NPX, 256>>>(attn);

    dim3 go(NPX / 64, CCH / 64, BB);
    out_kernel<<<go, 256>>>(x, attn, gamma, outp);
}

// round 6
// speedup vs baseline: 2.2682x; 2.2682x over previous
#include <cuda_runtime.h>
#include <cuda_bf16.h>
#include <cstdint>

// Problem constants
#define BB   4
#define CCH  256
#define NPX  4096     // W*H = 64*64
#define CQ   64       // C/4

#define OUT_ELEMS  ((size_t)BB * CCH * NPX)          // 4,194,304
#define ATTN_ELEMS ((size_t)BB * NPX * NPX)          // 67,108,864

// Scratch: Q^T and K^T stored as [b][n][cq] (K-contiguous for NT GEMM)
__device__ float g_Qt[BB * NPX * CQ];
__device__ float g_Kt[BB * NPX * CQ];
// Fallback attention buffer in case d_out only holds `out`
__device__ float g_attn_fb[ATTN_ELEMS];

// ===========================================================================
// Helpers (base sm_100-legal: ldmatrix + mma.sync, no tcgen05)
// ===========================================================================
__device__ __forceinline__ uint32_t smem_u32(const void* p) {
    uint32_t a;
    asm("{ .reg .u64 t; cvta.to.shared.u64 t, %1; cvt.u32.u64 %0, t; }"
        : "=r"(a) : "l"(p));
    return a;
}
// Pack two f32 into bf16x2 {lo, hi}. Single SASS op.
__device__ __forceinline__ uint32_t pack_bf16x2(float lo, float hi) {
    uint32_t r;
    asm("cvt.rn.bf16x2.f32 %0, %1, %2;" : "=r"(r) : "f"(hi), "f"(lo));
    return r;
}
__device__ __forceinline__ void ldmatrix_x4(uint32_t& r0, uint32_t& r1,
                                            uint32_t& r2, uint32_t& r3,
                                            uint32_t addr) {
    asm volatile("ldmatrix.sync.aligned.m8n8.x4.shared.b16 {%0,%1,%2,%3}, [%4];"
                 : "=r"(r0), "=r"(r1), "=r"(r2), "=r"(r3) : "r"(addr));
}
__device__ __forceinline__ void mma_16816(float* c, uint32_t a0, uint32_t a1,
                                          uint32_t a2, uint32_t a3,
                                          uint32_t b0, uint32_t b1) {
    asm volatile(
        "mma.sync.aligned.m16n8k16.row.col.f32.bf16.bf16.f32 "
        "{%0,%1,%2,%3}, {%4,%5,%6,%7}, {%8,%9}, {%0,%1,%2,%3};"
        : "+f"(c[0]), "+f"(c[1]), "+f"(c[2]), "+f"(c[3])
        : "r"(a0), "r"(a1), "r"(a2), "r"(a3), "r"(b0), "r"(b1));
}

// ---------------------------------------------------------------------------
// Kernel 1: projection. outT[b][n][oc] = sum_c w[oc][c] * x[b][c][n] + bias[oc]
// ---------------------------------------------------------------------------
__global__ void proj_kernel(const float* __restrict__ x,
                            const float* __restrict__ w,
                            const float* __restrict__ bias,
                            float* __restrict__ outT)
{
    const int b  = blockIdx.y;
    const int n0 = blockIdx.x * 64;
    const int tid = threadIdx.x;
    const int tx = tid & 15;        // n dimension
    const int ty = tid >> 4;        // oc dimension

    __shared__ __align__(16) float Xs[32][64];   // [c][n]
    __shared__ __align__(16) float Wt[32][68];   // [c][oc]

    const float* xb = x + (size_t)b * CCH * NPX;

    float acc[4][4];
#pragma unroll
    for (int i = 0; i < 4; i++)
#pragma unroll
        for (int j = 0; j < 4; j++) acc[i][j] = 0.f;

    for (int c0 = 0; c0 < CCH; c0 += 32) {
#pragma unroll
        for (int r = 0; r < 2; r++) {
            int idx = tid + r * 256;
            int cc  = idx >> 4;
            int nq  = (idx & 15) << 2;
            float4 v = *(const float4*)(xb + (size_t)(c0 + cc) * NPX + n0 + nq);
            *(float4*)(&Xs[cc][nq]) = v;
        }
#pragma unroll
        for (int r = 0; r < 2; r++) {
            int idx = tid + r * 256;
            int oc  = idx >> 3;
            int cq  = (idx & 7) << 2;
            float4 v = *(const float4*)(w + oc * CCH + c0 + cq);
            Wt[cq + 0][oc] = v.x;
            Wt[cq + 1][oc] = v.y;
            Wt[cq + 2][oc] = v.z;
            Wt[cq + 3][oc] = v.w;
        }
        __syncthreads();
#pragma unroll
        for (int cc = 0; cc < 32; cc++) {
            float4 a  = *(const float4*)(&Wt[cc][ty * 4]);
            float4 bv = *(const float4*)(&Xs[cc][tx * 4]);
            float av[4] = {a.x, a.y, a.z, a.w};
            float bw[4] = {bv.x, bv.y, bv.z, bv.w};
#pragma unroll
            for (int i = 0; i < 4; i++)
#pragma unroll
                for (int j = 0; j < 4; j++)
                    acc[i][j] = fmaf(av[i], bw[j], acc[i][j]);
        }
        __syncthreads();
    }

    float4 bb = *(const float4*)(bias + ty * 4);
    float b4[4] = {bb.x, bb.y, bb.z, bb.w};
    float* ob = outT + (size_t)b * NPX * CQ;
#pragma unroll
    for (int j = 0; j < 4; j++) {
        int n = n0 + tx * 4 + j;
        float4 v = make_float4(acc[0][j] + b4[0], acc[1][j] + b4[1],
                               acc[2][j] + b4[2], acc[3][j] + b4[3]);
        *(float4*)(ob + (size_t)n * CQ + ty * 4) = v;
    }
}

// ---------------------------------------------------------------------------
// Kernel 2: energy[b][i][j] = sum_c Qt[b][i][c] * Kt[b][j][c]   (K = 64)
// 128x128 tile, 8x8 microtile. 256 threads. fp32 (precision-critical).
// ---------------------------------------------------------------------------
__global__ void __launch_bounds__(256) energy_kernel(float* __restrict__ E)
{
    const int b  = blockIdx.z;
    const int i0 = blockIdx.y * 128;
    const int j0 = blockIdx.x * 128;
    const int tid = threadIdx.x;
    const int tx = tid & 15;        // j dim (8 cols)
    const int ty = tid >> 4;        // i dim (8 rows)

    __shared__ __align__(16) float Qs[16][132];   // [c][i]
    __shared__ __align__(16) float Ks[16][132];   // [c][j]

    const float* Qb = g_Qt + (size_t)b * NPX * CQ;
    const float* Kb = g_Kt + (size_t)b * NPX * CQ;

    float acc[8][8];
#pragma unroll
    for (int i = 0; i < 8; i++)
#pragma unroll
        for (int j = 0; j < 8; j++) acc[i][j] = 0.f;

    for (int c0 = 0; c0 < CQ; c0 += 16) {
#pragma unroll
        for (int r = 0; r < 2; r++) {
            int idx = tid + r * 256;          // 0..511
            int row = idx >> 2;               // 0..127
            int cq  = (idx & 3) << 2;         // 0,4,8,12
            float4 q = *(const float4*)(Qb + (size_t)(i0 + row) * CQ + c0 + cq);
            Qs[cq + 0][row] = q.x; Qs[cq + 1][row] = q.y;
            Qs[cq + 2][row] = q.z; Qs[cq + 3][row] = q.w;
            float4 k = *(const float4*)(Kb + (size_t)(j0 + row) * CQ + c0 + cq);
            Ks[cq + 0][row] = k.x; Ks[cq + 1][row] = k.y;
            Ks[cq + 2][row] = k.z; Ks[cq + 3][row] = k.w;
        }
        __syncthreads();

#pragma unroll
        for (int k = 0; k < 16; k++) {
            float4 a0 = *(const float4*)(&Qs[k][ty * 8]);
            float4 a1 = *(const float4*)(&Qs[k][ty * 8 + 4]);
            float4 b0 = *(const float4*)(&Ks[k][tx * 8]);
            float4 b1 = *(const float4*)(&Ks[k][tx * 8 + 4]);
            float av[8] = {a0.x, a0.y, a0.z, a0.w, a1.x, a1.y, a1.z, a1.w};
            float bw[8] = {b0.x, b0.y, b0.z, b0.w, b1.x, b1.y, b1.z, b1.w};
#pragma unroll
            for (int i = 0; i < 8; i++)
#pragma unroll
                for (int j = 0; j < 8; j++)
                    acc[i][j] = fmaf(av[i], bw[j], acc[i][j]);
        }
        __syncthreads();
    }

    float* Eb = E + (size_t)b * NPX * NPX;
#pragma unroll
    for (int i = 0; i < 8; i++) {
        int ii = i0 + ty * 8 + i;
        *(float4*)(Eb + (size_t)ii * NPX + j0 + tx * 8) =
            make_float4(acc[i][0], acc[i][1], acc[i][2], acc[i][3]);
        *(float4*)(Eb + (size_t)ii * NPX + j0 + tx * 8 + 4) =
            make_float4(acc[i][4], acc[i][5], acc[i][6], acc[i][7]);
    }
}

// ---------------------------------------------------------------------------
// Kernel 3: row softmax in place. One block (256 thr) per row of 4096.
// ---------------------------------------------------------------------------
__global__ void softmax_kernel(float* __restrict__ attn)
{
    __shared__ float red[8];
    const size_t row = blockIdx.x;
    float* r = attn + row * NPX;
    const int t = threadIdx.x;
    const int lane = t & 31;
    const int warp = t >> 5;

    float4 v[4];
#pragma unroll
    for (int u = 0; u < 4; u++)
        v[u] = *(const float4*)(r + (size_t)(t + u * 256) * 4);

    float mx = -3.402823e38f;
#pragma unroll
    for (int u = 0; u < 4; u++)
        mx = fmaxf(mx, fmaxf(fmaxf(v[u].x, v[u].y), fmaxf(v[u].z, v[u].w)));
#pragma unroll
    for (int o = 16; o > 0; o >>= 1)
        mx = fmaxf(mx, __shfl_xor_sync(0xFFFFFFFFu, mx, o));
    if (lane == 0) red[warp] = mx;
    __syncthreads();
    float rowmax = red[0];
#pragma unroll
    for (int u = 1; u < 8; u++) rowmax = fmaxf(rowmax, red[u]);
    __syncthreads();

    float s = 0.f;
#pragma unroll
    for (int u = 0; u < 4; u++) {
        v[u].x = __expf(v[u].x - rowmax);
        v[u].y = __expf(v[u].y - rowmax);
        v[u].z = __expf(v[u].z - rowmax);
        v[u].w = __expf(v[u].w - rowmax);
        s += v[u].x + v[u].y + v[u].z + v[u].w;
    }
#pragma unroll
    for (int o = 16; o > 0; o >>= 1)
        s += __shfl_xor_sync(0xFFFFFFFFu, s, o);
    if (lane == 0) red[warp] = s;
    __syncthreads();
    float total = 0.f;
#pragma unroll
    for (int u = 0; u < 8; u++) total += red[u];
    float inv = 1.0f / total;

#pragma unroll
    for (int u = 0; u < 4; u++) {
        v[u].x *= inv; v[u].y *= inv; v[u].z *= inv; v[u].w *= inv;
        *(float4*)(r + (size_t)(t + u * 256) * 4) = v[u];
    }
}

// ---------------------------------------------------------------------------
// Kernel 4 (mma.sync bf16): out[b][c][m] = gamma*sum_n x[b][c][n]*attn[b][m][n]
//                                         + x[b][c][m]
// CTA tile: M=256 (all channels -> attn read ONCE), N=64 pixels, K-chunk 32.
// 8 warps in 4(M) x 2(N); warp tile 64x32 via mma.m16n8k16.row.col bf16.
// Smem: pitch 64B/row, 16B-chunk swizzle  chunk ^ ((row>>1)&3)  -> ldmatrix
// conflict-free. Double-buffered, 1 syncthreads per K-chunk.
// ---------------------------------------------------------------------------
#define KC       32                         // K per chunk (bf16)
#define NKCHUNK  (NPX / KC)                 // 128
// smem byte offset for (row, f4col) where f4col indexes 8-byte halves (0..7)
__device__ __forceinline__ uint32_t swz_off(int row, int f4c) {
    uint32_t chunk = (uint32_t)(f4c >> 1) ^ (((uint32_t)row >> 1) & 3u);
    return (uint32_t)row * 64 + chunk * 16 + (uint32_t)(f4c & 1) * 8;
}

__global__ void __launch_bounds__(256, 1)
out_mma_kernel(const float* __restrict__ x,
               const float* __restrict__ attn,
               const float* __restrict__ gamma,
               float* __restrict__ outp)
{
    __shared__ __align__(128) uint8_t sA[2][256 * 64];   // 256 rows x 64B (32 bf16)
    __shared__ __align__(128) uint8_t sB[2][64 * 64];    // 64 rows x 64B

    const int b  = blockIdx.y;
    const int m0 = blockIdx.x * 64;
    const int tid = threadIdx.x;
    const int lane = tid & 31;
    const int wid = tid >> 5;
    const int warp_m = (wid & 3) * 64;      // 4 M groups of 64 rows
    const int warp_n = (wid >> 2) * 32;     // 2 N groups of 32 cols

    const float* A  = x    + (size_t)b * CCH * NPX;   // [256][4096]
    const float* Bm = attn + (size_t)b * NPX * NPX;   // [4096][4096]

    const uint32_t sA_u = smem_u32(&sA[0][0]);
    const uint32_t sB_u = smem_u32(&sB[0][0]);

    // loader indices
    const int arow0 = tid >> 3;             // A: rows tid/8 + i*32 (8 f4/row)
    const int af4   = tid & 7;
    // B: 512 f4 total, 2 per thread: row = (tid + i*256)>>3

    float acc[4][4][4];
#pragma unroll
    for (int mi = 0; mi < 4; mi++)
#pragma unroll
        for (int ni = 0; ni < 4; ni++)
#pragma unroll
            for (int q = 0; q < 4; q++) acc[mi][ni][q] = 0.f;

    // ---- prologue: chunk 0 -> stage 0
    {
#pragma unroll
        for (int i = 0; i < 8; i++) {
            const int row = arow0 + i * 32;
            float4 v = *(const float4*)(A + (size_t)row * NPX + af4 * 4);
            *(uint2*)(&sA[0][swz_off(row, af4)]) =
                make_uint2(pack_bf16x2(v.x, v.y), pack_bf16x2(v.z, v.w));
        }
#pragma unroll
        for (int i = 0; i < 2; i++) {
            const int idx = tid + i * 256;
            const int row = idx >> 3, f4c = idx & 7;
            float4 v = *(const float4*)(Bm + (size_t)(m0 + row) * NPX + f4c * 4);
            *(uint2*)(&sB[0][swz_off(row, f4c)]) =
                make_uint2(pack_bf16x2(v.x, v.y), pack_bf16x2(v.z, v.w));
        }
    }
    __syncthreads();

    for (int kc = 0; kc < NKCHUNK; kc++) {
        const int s = kc & 1;
        const bool has_next = (kc + 1 < NKCHUNK);
        float4 ra[8], rb[2];
        if (has_next) {
            const int k0 = (kc + 1) * KC;
#pragma unroll
            for (int i = 0; i < 8; i++) {
                const int row = arow0 + i * 32;
                ra[i] = *(const float4*)(A + (size_t)row * NPX + k0 + af4 * 4);
            }
#pragma unroll
            for (int i = 0; i < 2; i++) {
                const int idx = tid + i * 256;
                rb[i] = *(const float4*)(Bm + (size_t)(m0 + (idx >> 3)) * NPX
                                         + k0 + (idx & 7) * 4);
            }
        }

        const uint32_t aBase = sA_u + (uint32_t)s * (256 * 64);
        const uint32_t bBase = sB_u + (uint32_t)s * (64 * 64);
#pragma unroll
        for (int kk = 0; kk < 2; kk++) {
            uint32_t afr[4][4];
#pragma unroll
            for (int mi = 0; mi < 4; mi++) {
                const int row = warp_m + mi * 16 + (lane & 7) + ((lane >> 3) & 1) * 8;
                const uint32_t chunk = (uint32_t)(kk * 2 + (lane >> 4));
                const uint32_t addr = aBase + (uint32_t)row * 64
                    + ((chunk ^ (((uint32_t)row >> 1) & 3u)) * 16);
                ldmatrix_x4(afr[mi][0], afr[mi][1], afr[mi][2], afr[mi][3], addr);
            }
            uint32_t bfr[4][2];
#pragma unroll
            for (int ng = 0; ng < 2; ng++) {
                const int row = warp_n + ng * 16 + (lane & 7) + ((lane >> 4) & 1) * 8;
                const uint32_t chunk = (uint32_t)(kk * 2 + ((lane >> 3) & 1));
                const uint32_t addr = bBase + (uint32_t)row * 64
                    + ((chunk ^ (((uint32_t)row >> 1) & 3u)) * 16);
                uint32_t r0, r1, r2, r3;
                ldmatrix_x4(r0, r1, r2, r3, addr);
                bfr[ng * 2 + 0][0] = r0; bfr[ng * 2 + 0][1] = r1;
                bfr[ng * 2 + 1][0] = r2; bfr[ng * 2 + 1][1] = r3;
            }
#pragma unroll
            for (int mi = 0; mi < 4; mi++)
#pragma unroll
                for (int ni = 0; ni < 4; ni++)
                    mma_16816(acc[mi][ni], afr[mi][0], afr[mi][1],
                              afr[mi][2], afr[mi][3],
                              bfr[ni][0], bfr[ni][1]);
        }

        if (has_next) {
            const int sn = s ^ 1;
#pragma unroll
            for (int i = 0; i < 8; i++) {
                const int row = arow0 + i * 32;
                *(uint2*)(&sA[sn][swz_off(row, af4)]) =
                    make_uint2(pack_bf16x2(ra[i].x, ra[i].y),
                               pack_bf16x2(ra[i].z, ra[i].w));
            }
#pragma unroll
            for (int i = 0; i < 2; i++) {
                const int idx = tid + i * 256;
                *(uint2*)(&sB[sn][swz_off(idx >> 3, idx & 7)]) =
                    make_uint2(pack_bf16x2(rb[i].x, rb[i].y),
                               pack_bf16x2(rb[i].z, rb[i].w));
            }
        }
        __syncthreads();
    }

    // ---- epilogue: out = gamma*acc + x
    const float g = gamma[0];
    float* ob = outp + (size_t)b * CCH * NPX;
#pragma unroll
    for (int mi = 0; mi < 4; mi++) {
        const int c0 = warp_m + mi * 16 + (lane >> 2);
#pragma unroll
        for (int ni = 0; ni < 4; ni++) {
            const int m = m0 + warp_n + ni * 8 + (lane & 3) * 2;
            {
                const float2 xv = *(const float2*)(A + (size_t)c0 * NPX + m);
                float2 v = make_float2(fmaf(g, acc[mi][ni][0], xv.x),
                                       fmaf(g, acc[mi][ni][1], xv.y));
                *(float2*)(ob + (size_t)c0 * NPX + m) = v;
            }
            {
                const int c1 = c0 + 8;
                const float2 xv = *(const float2*)(A + (size_t)c1 * NPX + m);
                float2 v = make_float2(fmaf(g, acc[mi][ni][2], xv.x),
                                       fmaf(g, acc[mi][ni][3], xv.y));
                *(float2*)(ob + (size_t)c1 * NPX + m) = v;
            }
        }
    }
}

// ---------------------------------------------------------------------------
// Launch
// ---------------------------------------------------------------------------
extern "C" void kernel_launch(void* const* d_in, const int* in_sizes, int n_in,
                              void* d_out, int out_size)
{
    const float* x     = (const float*)d_in[0];
    const float* w_q   = (const float*)d_in[1];
    const float* b_q   = (const float*)d_in[2];
    const float* w_k   = (const float*)d_in[3];
    const float* b_k   = (const float*)d_in[4];
    const float* gamma = (const float*)d_in[5];

    float* outp = (float*)d_out;

    float* attn;
    if ((size_t)out_size >= OUT_ELEMS + ATTN_ELEMS) {
        attn = outp + OUT_ELEMS;
    } else {
        void* p = nullptr;
        cudaGetSymbolAddress(&p, g_attn_fb);
        attn = (float*)p;
    }

    void* pq = nullptr; void* pk = nullptr;
    cudaGetSymbolAddress(&pq, g_Qt);
    cudaGetSymbolAddress(&pk, g_Kt);

    dim3 gp(NPX / 64, BB);
    proj_kernel<<<gp, 256>>>(x, w_q, b_q, (float*)pq);
    proj_kernel<<<gp, 256>>>(x, w_k, b_k, (float*)pk);

    dim3 ge(NPX / 128, NPX / 128, BB);
    energy_kernel<<<ge, 256>>>(attn);

    softmax_kernel<<<BB * NPX, 256>>>(attn);

    dim3 go(NPX / 64, BB);
    out_mma_kernel<<<go, 256>>>(x, attn, gamma, outp);
}